// round 11
// baseline (speedup 1.0000x reference)
#include <cuda_runtime.h>
#include <cuda_fp16.h>
#include <mma.h>
#include <cstdint>

using namespace nvcuda;

#define NN     20000
#define EMB    128
#define HID    512
#define CN     1024
#define MTILES 157              // ceil(20000/128)
#define MPAD   (MTILES * 128)   // 20096
#define KP     256              // storage: 2 fp16 splits of 128
#define EMAX   320000

// -------- scratch (no allocations allowed) --------
__device__ float g_C[(size_t)MPAD * CN];                      // 82.3 MB
__device__ __align__(16) __half g_Ahf[(size_t)MPAD * KP];     // 10.3 MB: [a0|a1]
__device__ __align__(16) __half g_Bhf[(size_t)KP * CN];       // 524 KB: [b0;b1]
__device__ int                g_nmax[NN];
__device__ unsigned long long g_nsum[NN];
__device__ int                g_cnt[NN];        // histogram -> scatter cursor
__device__ int                g_off[NN + 1];    // CSR offsets (persist)
__device__ int                g_perm[EMAX];     // original edge id, row-sorted
__device__ int                g_cs[EMAX];       // col, row-sorted

#define FIXSCALE 4398046511104.0   // 2^42

__device__ __forceinline__ int f2ord(float f) {
    int i = __float_as_int(f);
    return i >= 0 ? i : (i ^ 0x7FFFFFFF);
}
__device__ __forceinline__ float ord2f(int i) {
    return __int_as_float(i >= 0 ? i : (i ^ 0x7FFFFFFF));
}
__device__ __forceinline__ uint32_t smem_u32(const void* p) {
    uint32_t a;
    asm("{ .reg .u64 t; cvta.to.shared.u64 t, %1; cvt.u32.u64 %0, t; }" : "=r"(a) : "l"(p));
    return a;
}
__device__ __forceinline__ void cpa16(uint32_t dst, const void* src) {
    asm volatile("cp.async.cg.shared.global [%0], [%1], 16;" :: "r"(dst), "l"(src));
}

// -------- kernel 0: init (only the sort cursor needs zeroing) --------
__global__ void k_init() {
    int i = blockIdx.x * blockDim.x + threadIdx.x;
    if (i < NN) g_cnt[i] = 0;
}

// -------- sort 1: histogram, 4 edges/thread for atomic ILP --------
__global__ void k_hist(const int* __restrict__ row, int E) {
    int t = blockIdx.x * blockDim.x + threadIdx.x;
    int base = t * 4;
    if (base + 4 <= E) {
        int4 r4 = *(const int4*)(row + base);
        atomicAdd(&g_cnt[r4.x], 1);
        atomicAdd(&g_cnt[r4.y], 1);
        atomicAdd(&g_cnt[r4.z], 1);
        atomicAdd(&g_cnt[r4.w], 1);
    } else {
        for (int e = base; e < E; e++) atomicAdd(&g_cnt[row[e]], 1);
    }
}

// -------- sort 2: exclusive scan (single block) --------
#define SCAN_PER 20   // 1024*20 = 20480 >= NN
__global__ void __launch_bounds__(1024) k_scan() {
    __shared__ int ts[1024];
    int tid = threadIdx.x;
    int base = tid * SCAN_PER;
    int loc[SCAN_PER];
    int s = 0;
#pragma unroll
    for (int i = 0; i < SCAN_PER; i++) {
        int idx = base + i;
        loc[i] = (idx < NN) ? g_cnt[idx] : 0;
        s += loc[i];
    }
    ts[tid] = s;
    __syncthreads();
    for (int off = 1; off < 1024; off <<= 1) {
        int v = (tid >= off) ? ts[tid - off] : 0;
        __syncthreads();
        ts[tid] += v;
        __syncthreads();
    }
    int excl = ts[tid] - s;
#pragma unroll
    for (int i = 0; i < SCAN_PER; i++) {
        int idx = base + i;
        if (idx < NN) { g_off[idx] = excl; g_cnt[idx] = excl; }
        excl += loc[i];
    }
    if (tid == 1023) g_off[NN] = ts[1023];
}

// -------- sort 3: scatter (edge id + col), 4 edges/thread --------
__global__ void k_scatter(const int* __restrict__ row, const int* __restrict__ col, int E) {
    int t = blockIdx.x * blockDim.x + threadIdx.x;
    int base = t * 4;
    if (base + 4 <= E) {
        int4 r4 = *(const int4*)(row + base);
        int4 c4 = *(const int4*)(col + base);
        int p0 = atomicAdd(&g_cnt[r4.x], 1);
        int p1 = atomicAdd(&g_cnt[r4.y], 1);
        int p2 = atomicAdd(&g_cnt[r4.z], 1);
        int p3 = atomicAdd(&g_cnt[r4.w], 1);
        g_perm[p0] = base;     g_cs[p0] = c4.x;
        g_perm[p1] = base + 1; g_cs[p1] = c4.y;
        g_perm[p2] = base + 2; g_cs[p2] = c4.z;
        g_perm[p3] = base + 3; g_cs[p3] = c4.w;
    } else {
        for (int e = base; e < E; e++) {
            int p = atomicAdd(&g_cnt[row[e]], 1);
            g_perm[p] = e; g_cs[p] = col[e];
        }
    }
}

// -------- kernel 1a: 2-way fp16 split of h -> A'[MPAD][256] row-major --------
__global__ void k_split_a(const float* __restrict__ h) {
    int t = blockIdx.x * blockDim.x + threadIdx.x;
    int m = t >> 4;
    if (m >= MPAD) return;
    int k = (t & 15) << 3;

    float v[8];
    if (m < NN) {
        float4 v0 = *(const float4*)(h + (size_t)m * EMB + k);
        float4 v1 = *(const float4*)(h + (size_t)m * EMB + k + 4);
        v[0]=v0.x; v[1]=v0.y; v[2]=v0.z; v[3]=v0.w;
        v[4]=v1.x; v[5]=v1.y; v[6]=v1.z; v[7]=v1.w;
    } else {
#pragma unroll
        for (int i = 0; i < 8; i++) v[i] = 0.f;
    }

#pragma unroll
    for (int s = 0; s < 2; s++) {
        unsigned short hs[8];
#pragma unroll
        for (int i = 0; i < 8; i++) {
            __half b = __float2half_rn(v[i]);
            hs[i] = __half_as_ushort(b);
            v[i] -= __half2float(b);
        }
        uint4 pk;
        pk.x = (uint32_t)hs[0] | ((uint32_t)hs[1] << 16);
        pk.y = (uint32_t)hs[2] | ((uint32_t)hs[3] << 16);
        pk.z = (uint32_t)hs[4] | ((uint32_t)hs[5] << 16);
        pk.w = (uint32_t)hs[6] | ((uint32_t)hs[7] << 16);
        *(uint4*)(g_Ahf + (size_t)m * KP + s * 128 + k) = pk;
    }
}

// -------- kernel 1b: 2-way fp16 split of [W1_top|W1_bot] -> B'[256][1024] --------
__global__ void k_split_b(const float* __restrict__ W1) {
    int t = blockIdx.x * blockDim.x + threadIdx.x;
    if (t >= 128 * 256) return;
    int k = t >> 8;
    int n = (t & 255) << 2;

    float w[4];
#pragma unroll
    for (int i = 0; i < 4; i++) {
        int nn = n + i;
        w[i] = (nn < HID) ? W1[(size_t)k * HID + nn]
                          : W1[(size_t)(EMB + k) * HID + (nn - HID)];
    }
#pragma unroll
    for (int s = 0; s < 2; s++) {
        unsigned short hs[4];
#pragma unroll
        for (int i = 0; i < 4; i++) {
            __half b = __float2half_rn(w[i]);
            hs[i] = __half_as_ushort(b);
            w[i] -= __half2float(b);
        }
        uint2 pk;
        pk.x = (uint32_t)hs[0] | ((uint32_t)hs[1] << 16);
        pk.y = (uint32_t)hs[2] | ((uint32_t)hs[3] << 16);
        *(uint2*)(g_Bhf + (size_t)(s * 128 + k) * CN + n) = pk;
    }
}

// -------- kernel 2: WMMA fp16 GEMM, 3-term split-product, 4-stage pipeline --------
#define KC      32
#define NPAIR   3
#define NCH     (NPAIR * 4)
#define A_LDM   40
#define B_LDM   136
#define STAGES  4
#define A_BYTES (128 * A_LDM * 2)
#define B_BYTES (KC * B_LDM * 2)
#define STG_BYTES (A_BYTES + B_BYTES)
#define SMEM_DYN (STAGES * STG_BYTES + 16 * B_LDM * 4)

__constant__ int c_PS[NPAIR] = {0, 0, 1};
__constant__ int c_PT[NPAIR] = {0, 1, 0};

__global__ void __launch_bounds__(256) k_wgemm(const float* __restrict__ b1) {
    extern __shared__ char dsm[];
    float* biasS = (float*)(dsm + STAGES * STG_BYTES);

    const int tid = threadIdx.x;
    const int wid = tid >> 5;
    const int nt  = blockIdx.x;
    const int mt  = blockIdx.y;
    const int warp_m = wid & 1;
    const int warp_n = wid >> 1;

    for (int idx = tid; idx < 16 * 128; idx += 256) {
        int r = idx >> 7, c = idx & 127;
        biasS[r * B_LDM + c] = (nt < 4) ? b1[nt * 128 + c] : 0.f;
    }

    const __half* gA = g_Ahf + (size_t)(mt * 128) * KP;
    const __half* gB = g_Bhf + (size_t)nt * 128;

    auto stage_body = [&](int c) {
        int buf = c & (STAGES - 1);
        int p   = c >> 2;
        int sub = c & 3;
        int aoff = c_PS[p] * 128 + sub * KC;
        int boff = c_PT[p] * 128 + sub * KC;
        char* sA = dsm + buf * STG_BYTES;
        char* sB = sA + A_BYTES;
#pragma unroll
        for (int q = 0; q < 2; q++) {
            int l = tid + q * 256;
            int r = l >> 2, cc = (l & 3) * 8;
            cpa16(smem_u32(sA + r * (A_LDM * 2) + cc * 2),
                  gA + (size_t)r * KP + aoff + cc);
        }
#pragma unroll
        for (int q = 0; q < 2; q++) {
            int l = tid + q * 256;
            int r = l >> 4, cc = (l & 15) * 8;
            cpa16(smem_u32(sB + r * (B_LDM * 2) + cc * 2),
                  gB + (size_t)(boff + r) * CN + cc);
        }
    };

    wmma::fragment<wmma::accumulator, 16, 16, 16, float> acc[4][2];
#pragma unroll
    for (int i = 0; i < 4; i++)
#pragma unroll
        for (int j = 0; j < 2; j++) wmma::fill_fragment(acc[i][j], 0.f);

#pragma unroll
    for (int c = 0; c < STAGES - 1; c++) {
        stage_body(c);
        asm volatile("cp.async.commit_group;" ::: "memory");
    }

    for (int c = 0; c < NCH; c++) {
        asm volatile("cp.async.wait_group %0;" :: "n"(STAGES - 2) : "memory");
        __syncthreads();

        int nx = c + STAGES - 1;
        if (nx < NCH) stage_body(nx);
        asm volatile("cp.async.commit_group;" ::: "memory");

        int buf = c & (STAGES - 1);
        __half* As = (__half*)(dsm + buf * STG_BYTES);
        __half* Bs = (__half*)(dsm + buf * STG_BYTES + A_BYTES);

#pragma unroll
        for (int kk = 0; kk < KC; kk += 16) {
            wmma::fragment<wmma::matrix_a, 16, 16, 16, __half, wmma::row_major> af[4];
            wmma::fragment<wmma::matrix_b, 16, 16, 16, __half, wmma::row_major> bf[2];
#pragma unroll
            for (int i = 0; i < 4; i++)
                wmma::load_matrix_sync(af[i],
                    As + (size_t)(warp_m * 64 + i * 16) * A_LDM + kk, A_LDM);
#pragma unroll
            for (int j = 0; j < 2; j++)
                wmma::load_matrix_sync(bf[j],
                    Bs + (size_t)kk * B_LDM + warp_n * 32 + j * 16, B_LDM);
#pragma unroll
            for (int i = 0; i < 4; i++)
#pragma unroll
                for (int j = 0; j < 2; j++)
                    wmma::mma_sync(acc[i][j], af[i], bf[j], acc[i][j]);
        }
    }

    wmma::fragment<wmma::accumulator, 16, 16, 16, float> cb[2];
#pragma unroll
    for (int j = 0; j < 2; j++) {
        wmma::load_matrix_sync(cb[j], biasS + warp_n * 32 + j * 16, B_LDM,
                               wmma::mem_row_major);
#pragma unroll
        for (int i = 0; i < 4; i++)
#pragma unroll
            for (int e = 0; e < acc[i][j].num_elements; e++)
                acc[i][j].x[e] += cb[j].x[e];
    }

#pragma unroll
    for (int i = 0; i < 4; i++) {
        int rowg = mt * 128 + warp_m * 64 + i * 16;
#pragma unroll
        for (int j = 0; j < 2; j++) {
            float* dst = g_C + (size_t)rowg * CN + nt * 128 + warp_n * 32 + j * 16;
            wmma::store_matrix_sync(dst, acc[i][j], CN, wmma::mem_row_major);
        }
    }
}

// -------- kernel 3: warp per node — scores + segment max + exact exp-sum --------
// CA row & W2 in registers; per edge only CB row is loaded. No atomics.
__global__ void __launch_bounds__(256) k_edge2(const float* __restrict__ W2,
                                               const float* __restrict__ b2,
                                               const float* __restrict__ u,
                                               float* __restrict__ out, int E) {
    int gw   = (blockIdx.x * blockDim.x + threadIdx.x) >> 5;
    int lane = threadIdx.x & 31;
    if (gw >= NN) return;
    int off0 = g_off[gw], off1 = g_off[gw + 1];
    int deg = off1 - off0;
    if (deg == 0) return;

    // lane holds k = i*128 + lane*4 (+0..3), i in 0..3 -> covers k in [0,512)
    float4 ca[4], w[4];
#pragma unroll
    for (int i = 0; i < 4; i++) {
        int k = i * 128 + lane * 4;
        ca[i] = *(const float4*)(g_C + (size_t)gw * CN + k);
        w[i]  = __ldg((const float4*)(W2 + k));
    }
    float bias2 = b2[0];

    float m = -1e30f;
    float scr[2];                 // scores for edges j = lane, lane+32

    int c_cur = g_cs[off0];
    float4 cb[4];
#pragma unroll
    for (int i = 0; i < 4; i++)
        cb[i] = *(const float4*)(g_C + (size_t)c_cur * CN + HID + i * 128 + lane * 4);

    for (int j = 0; j < deg; j++) {
        // prefetch next edge's CB
        float4 nb[4];
        if (j + 1 < deg) {
            int c_nx = g_cs[off0 + j + 1];
#pragma unroll
            for (int i = 0; i < 4; i++)
                nb[i] = *(const float4*)(g_C + (size_t)c_nx * CN + HID + i * 128 + lane * 4);
        }

        float acc = 0.f;
#pragma unroll
        for (int i = 0; i < 4; i++) {
            acc = fmaf(fmaxf(ca[i].x + cb[i].x, 0.f), w[i].x, acc);
            acc = fmaf(fmaxf(ca[i].y + cb[i].y, 0.f), w[i].y, acc);
            acc = fmaf(fmaxf(ca[i].z + cb[i].z, 0.f), w[i].z, acc);
            acc = fmaf(fmaxf(ca[i].w + cb[i].w, 0.f), w[i].w, acc);
        }
#pragma unroll
        for (int o = 16; o; o >>= 1) acc += __shfl_xor_sync(0xFFFFFFFFu, acc, o);
        float s = acc + bias2;    // all lanes hold s

        if (lane == (j & 31)) scr[j >> 5] = s;   // register-resident for j<64
        m = fmaxf(m, s);
        if (lane == 0) out[g_perm[off0 + j]] = s;

#pragma unroll
        for (int i = 0; i < 4; i++) cb[i] = nb[i];
    }

    // rare deg>64 tail: scores already in gmem; make warp's own writes visible
    if (deg > 64) __threadfence_block();

    // exact fixed-point exp-sum (order-independent)
    unsigned long long q = 0ull;
    for (int j = lane; j < deg; j += 32) {
        float s = (j < 64) ? scr[j >> 5] : out[g_perm[off0 + j]];
        float ex = expf(s - m);
        q += (unsigned long long)((double)ex * FIXSCALE);
    }
#pragma unroll
    for (int o = 16; o; o >>= 1) q += __shfl_xor_sync(0xFFFFFFFFu, q, o);

    if (lane == 0) {
        g_nmax[gw] = f2ord(m);
        g_nsum[gw] = q;
    }
}

// -------- kernel 4: outputs --------
__global__ void k_final(const float* __restrict__ scores, const int* __restrict__ row,
                        const float* __restrict__ u, const int* __restrict__ edge_mask,
                        const int* __restrict__ hier, float* __restrict__ out, int E) {
    int e = blockIdx.x * blockDim.x + threadIdx.x;
    if (e >= E) return;
    int r = row[e];
    float s = scores[e];
    float m = ord2f(g_nmax[r]);
    float ex = expf(s - m);
    float ssum = (float)((double)g_nsum[r] * (1.0 / FIXSCALE));
    float p = fminf(ex / ssum, 1.0f);

    float logits = logf(p) - log1pf(-p);
    float uu = u[e];
    float x = logits + (logf(uu) - log1pf(-uu));
    float y = 1.0f / (1.0f + expf(-x));
    bool hard = (y > 0.5f);

    int nm = hard ? (hier[0] + 1) : edge_mask[e];
    out[(size_t)E + e]     = hard ? 1.0f : 0.0f;
    out[(size_t)2 * E + e] = (float)nm;
    out[(size_t)3 * E + e] = (nm > 0) ? s : 0.0f;
    out[(size_t)4 * E + e] = (nm == -1) ? -s : 0.0f;
}

extern "C" void kernel_launch(void* const* d_in, const int* in_sizes, int n_in,
                              void* d_out, int out_size) {
    const float* h     = (const float*)d_in[0];
    const float* W1    = (const float*)d_in[1];
    const float* b1    = (const float*)d_in[2];
    const float* W2    = (const float*)d_in[3];
    const float* b2    = (const float*)d_in[4];
    const float* u     = (const float*)d_in[5];
    const int*   row   = (const int*)d_in[6];
    const int*   col   = (const int*)d_in[7];
    const int*   emask = (const int*)d_in[8];
    const int*   hier  = (const int*)d_in[9];
    float* out = (float*)d_out;
    int E = in_sizes[5];

    static bool attr_done = false;
    if (!attr_done) {
        cudaFuncSetAttribute(k_wgemm, cudaFuncAttributeMaxDynamicSharedMemorySize, SMEM_DYN);
        attr_done = true;
    }

    k_init<<<(NN + 255) / 256, 256>>>();
    k_hist<<<(E / 4 + 255) / 256, 256>>>(row, E);
    k_scan<<<1, 1024>>>();
    k_scatter<<<(E / 4 + 255) / 256, 256>>>(row, col, E);
    k_split_a<<<(MPAD * 16 + 255) / 256, 256>>>(h);
    k_split_b<<<(128 * 256 + 255) / 256, 256>>>(W1);
    k_wgemm<<<dim3(8, MTILES), 256, SMEM_DYN>>>(b1);
    k_edge2<<<(NN * 32 + 255) / 256, 256>>>(W2, b2, u, out, E);
    k_final<<<(E + 255) / 256, 256>>>(out, row, u, emask, hier, out, E);
}

// round 12
// speedup vs baseline: 1.2425x; 1.2425x over previous
#include <cuda_runtime.h>
#include <cuda_fp16.h>
#include <mma.h>
#include <cstdint>

using namespace nvcuda;

#define NN     20000
#define EMB    128
#define HID    512
#define CN     1024
#define MTILES 157              // ceil(20000/128)
#define MPAD   (MTILES * 128)   // 20096
#define KP     256              // storage: 2 fp16 splits of 128

// -------- scratch (no allocations allowed) --------
__device__ float g_C[(size_t)MPAD * CN];                      // 82.3 MB
__device__ __align__(16) __half g_Ahf[(size_t)MPAD * KP];     // 10.3 MB: [a0|a1]
__device__ __align__(16) __half g_Bhf[(size_t)KP * CN];       // 524 KB: [b0;b1]
__device__ int                g_nmax[NN];
__device__ unsigned long long g_nsum[NN];

#define FIXSCALE 4398046511104.0   // 2^42

__device__ __forceinline__ int f2ord(float f) {
    int i = __float_as_int(f);
    return i >= 0 ? i : (i ^ 0x7FFFFFFF);
}
__device__ __forceinline__ float ord2f(int i) {
    return __int_as_float(i >= 0 ? i : (i ^ 0x7FFFFFFF));
}
__device__ __forceinline__ uint32_t smem_u32(const void* p) {
    uint32_t a;
    asm("{ .reg .u64 t; cvta.to.shared.u64 t, %1; cvt.u32.u64 %0, t; }" : "=r"(a) : "l"(p));
    return a;
}
__device__ __forceinline__ void cpa16(uint32_t dst, const void* src) {
    asm volatile("cp.async.cg.shared.global [%0], [%1], 16;" :: "r"(dst), "l"(src));
}

// -------- kernel 0: init --------
__global__ void k_init() {
    int i = blockIdx.x * blockDim.x + threadIdx.x;
    if (i < NN) {
        g_nmax[i] = (int)0x80000000;
        g_nsum[i] = 0ull;
    }
}

// -------- kernel 1a: 2-way fp16 split of h -> A'[MPAD][256] row-major --------
__global__ void k_split_a(const float* __restrict__ h) {
    int t = blockIdx.x * blockDim.x + threadIdx.x;
    int m = t >> 4;
    if (m >= MPAD) return;
    int k = (t & 15) << 3;

    float v[8];
    if (m < NN) {
        float4 v0 = *(const float4*)(h + (size_t)m * EMB + k);
        float4 v1 = *(const float4*)(h + (size_t)m * EMB + k + 4);
        v[0]=v0.x; v[1]=v0.y; v[2]=v0.z; v[3]=v0.w;
        v[4]=v1.x; v[5]=v1.y; v[6]=v1.z; v[7]=v1.w;
    } else {
#pragma unroll
        for (int i = 0; i < 8; i++) v[i] = 0.f;
    }

#pragma unroll
    for (int s = 0; s < 2; s++) {
        unsigned short hs[8];
#pragma unroll
        for (int i = 0; i < 8; i++) {
            __half b = __float2half_rn(v[i]);
            hs[i] = __half_as_ushort(b);
            v[i] -= __half2float(b);
        }
        uint4 pk;
        pk.x = (uint32_t)hs[0] | ((uint32_t)hs[1] << 16);
        pk.y = (uint32_t)hs[2] | ((uint32_t)hs[3] << 16);
        pk.z = (uint32_t)hs[4] | ((uint32_t)hs[5] << 16);
        pk.w = (uint32_t)hs[6] | ((uint32_t)hs[7] << 16);
        *(uint4*)(g_Ahf + (size_t)m * KP + s * 128 + k) = pk;
    }
}

// -------- kernel 1b: 2-way fp16 split of [W1_top|W1_bot] -> B'[256][1024] --------
__global__ void k_split_b(const float* __restrict__ W1) {
    int t = blockIdx.x * blockDim.x + threadIdx.x;
    if (t >= 128 * 256) return;
    int k = t >> 8;
    int n = (t & 255) << 2;

    float w[4];
#pragma unroll
    for (int i = 0; i < 4; i++) {
        int nn = n + i;
        w[i] = (nn < HID) ? W1[(size_t)k * HID + nn]
                          : W1[(size_t)(EMB + k) * HID + (nn - HID)];
    }
#pragma unroll
    for (int s = 0; s < 2; s++) {
        unsigned short hs[4];
#pragma unroll
        for (int i = 0; i < 4; i++) {
            __half b = __float2half_rn(w[i]);
            hs[i] = __half_as_ushort(b);
            w[i] -= __half2float(b);
        }
        uint2 pk;
        pk.x = (uint32_t)hs[0] | ((uint32_t)hs[1] << 16);
        pk.y = (uint32_t)hs[2] | ((uint32_t)hs[3] << 16);
        *(uint2*)(g_Bhf + (size_t)(s * 128 + k) * CN + n) = pk;
    }
}

// -------- kernel 2: WMMA fp16 GEMM, 3-term split-product, 4-stage pipeline --------
// C = A0B0 + A0B1 + A1B0   (dropped A1B1 ~ 2^-22)
#define KC      32
#define NPAIR   3
#define NCH     (NPAIR * 4)        // 12 chunks of KC=32
#define A_LDM   40
#define B_LDM   136
#define STAGES  4
#define A_BYTES (128 * A_LDM * 2)
#define B_BYTES (KC * B_LDM * 2)
#define STG_BYTES (A_BYTES + B_BYTES)
#define SMEM_DYN (STAGES * STG_BYTES + 16 * B_LDM * 4)

__constant__ int c_PS[NPAIR] = {0, 0, 1};
__constant__ int c_PT[NPAIR] = {0, 1, 0};

__global__ void __launch_bounds__(256) k_wgemm(const float* __restrict__ b1) {
    extern __shared__ char dsm[];
    float* biasS = (float*)(dsm + STAGES * STG_BYTES);

    const int tid = threadIdx.x;
    const int wid = tid >> 5;
    const int nt  = blockIdx.x;
    const int mt  = blockIdx.y;
    const int warp_m = wid & 1;
    const int warp_n = wid >> 1;

    for (int idx = tid; idx < 16 * 128; idx += 256) {
        int r = idx >> 7, c = idx & 127;
        biasS[r * B_LDM + c] = (nt < 4) ? b1[nt * 128 + c] : 0.f;
    }

    const __half* gA = g_Ahf + (size_t)(mt * 128) * KP;
    const __half* gB = g_Bhf + (size_t)nt * 128;

    auto stage_body = [&](int c) {
        int buf = c & (STAGES - 1);
        int p   = c >> 2;
        int sub = c & 3;
        int aoff = c_PS[p] * 128 + sub * KC;
        int boff = c_PT[p] * 128 + sub * KC;
        char* sA = dsm + buf * STG_BYTES;
        char* sB = sA + A_BYTES;
#pragma unroll
        for (int q = 0; q < 2; q++) {
            int l = tid + q * 256;
            int r = l >> 2, cc = (l & 3) * 8;
            cpa16(smem_u32(sA + r * (A_LDM * 2) + cc * 2),
                  gA + (size_t)r * KP + aoff + cc);
        }
#pragma unroll
        for (int q = 0; q < 2; q++) {
            int l = tid + q * 256;
            int r = l >> 4, cc = (l & 15) * 8;
            cpa16(smem_u32(sB + r * (B_LDM * 2) + cc * 2),
                  gB + (size_t)(boff + r) * CN + cc);
        }
    };

    wmma::fragment<wmma::accumulator, 16, 16, 16, float> acc[4][2];
#pragma unroll
    for (int i = 0; i < 4; i++)
#pragma unroll
        for (int j = 0; j < 2; j++) wmma::fill_fragment(acc[i][j], 0.f);

#pragma unroll
    for (int c = 0; c < STAGES - 1; c++) {
        stage_body(c);
        asm volatile("cp.async.commit_group;" ::: "memory");
    }

    for (int c = 0; c < NCH; c++) {
        asm volatile("cp.async.wait_group %0;" :: "n"(STAGES - 2) : "memory");
        __syncthreads();

        int nx = c + STAGES - 1;
        if (nx < NCH) stage_body(nx);
        asm volatile("cp.async.commit_group;" ::: "memory");

        int buf = c & (STAGES - 1);
        __half* As = (__half*)(dsm + buf * STG_BYTES);
        __half* Bs = (__half*)(dsm + buf * STG_BYTES + A_BYTES);

#pragma unroll
        for (int kk = 0; kk < KC; kk += 16) {
            wmma::fragment<wmma::matrix_a, 16, 16, 16, __half, wmma::row_major> af[4];
            wmma::fragment<wmma::matrix_b, 16, 16, 16, __half, wmma::row_major> bf[2];
#pragma unroll
            for (int i = 0; i < 4; i++)
                wmma::load_matrix_sync(af[i],
                    As + (size_t)(warp_m * 64 + i * 16) * A_LDM + kk, A_LDM);
#pragma unroll
            for (int j = 0; j < 2; j++)
                wmma::load_matrix_sync(bf[j],
                    Bs + (size_t)kk * B_LDM + warp_n * 32 + j * 16, B_LDM);
#pragma unroll
            for (int i = 0; i < 4; i++)
#pragma unroll
                for (int j = 0; j < 2; j++)
                    wmma::mma_sync(acc[i][j], af[i], bf[j], acc[i][j]);
        }
    }

    wmma::fragment<wmma::accumulator, 16, 16, 16, float> cb[2];
#pragma unroll
    for (int j = 0; j < 2; j++) {
        wmma::load_matrix_sync(cb[j], biasS + warp_n * 32 + j * 16, B_LDM,
                               wmma::mem_row_major);
#pragma unroll
        for (int i = 0; i < 4; i++)
#pragma unroll
            for (int e = 0; e < acc[i][j].num_elements; e++)
                acc[i][j].x[e] += cb[j].x[e];
    }

#pragma unroll
    for (int i = 0; i < 4; i++) {
        int rowg = mt * 128 + warp_m * 64 + i * 16;
#pragma unroll
        for (int j = 0; j < 2; j++) {
            float* dst = g_C + (size_t)rowg * CN + nt * 128 + warp_n * 32 + j * 16;
            wmma::store_matrix_sync(dst, acc[i][j], CN, wmma::mem_row_major);
        }
    }
}

// -------- kernel 3: 16 lanes per edge, 2 edges interleaved per half-warp --------
__global__ void __launch_bounds__(256) k_edge(const int* __restrict__ row,
                                              const int* __restrict__ col,
                                              const float* __restrict__ W2,
                                              const float* __restrict__ b2,
                                              float* __restrict__ scores_out, int E) {
    int gt   = blockIdx.x * blockDim.x + threadIdx.x;
    int warp = gt >> 5;
    int lane = gt & 31;
    int e0   = warp * 4 + (lane >> 4) * 2;   // this half-warp: edges e0, e0+1
    int sub  = lane & 15;
    if (e0 >= E) return;
    int e1 = e0 + 1;
    bool has1 = (e1 < E);

    int r0 = row[e0], c0 = col[e0];
    int r1 = has1 ? row[e1] : r0;
    int c1 = has1 ? col[e1] : c0;

    const float4* pa0 = (const float4*)(g_C + (size_t)r0 * CN);
    const float4* pb0 = (const float4*)(g_C + (size_t)c0 * CN + HID);
    const float4* pa1 = (const float4*)(g_C + (size_t)r1 * CN);
    const float4* pb1 = (const float4*)(g_C + (size_t)c1 * CN + HID);
    const float4* pw  = (const float4*)W2;

    float acc0 = 0.f, acc1 = 0.f;
#pragma unroll
    for (int i = 0; i < 8; i++) {
        int idx = sub + i * 16;
        float4 w  = __ldg(&pw[idx]);
        float4 a0 = pa0[idx];
        float4 b0 = pb0[idx];
        float4 a1 = pa1[idx];
        float4 b1 = pb1[idx];
        acc0 = fmaf(fmaxf(a0.x + b0.x, 0.f), w.x, acc0);
        acc0 = fmaf(fmaxf(a0.y + b0.y, 0.f), w.y, acc0);
        acc0 = fmaf(fmaxf(a0.z + b0.z, 0.f), w.z, acc0);
        acc0 = fmaf(fmaxf(a0.w + b0.w, 0.f), w.w, acc0);
        acc1 = fmaf(fmaxf(a1.x + b1.x, 0.f), w.x, acc1);
        acc1 = fmaf(fmaxf(a1.y + b1.y, 0.f), w.y, acc1);
        acc1 = fmaf(fmaxf(a1.z + b1.z, 0.f), w.z, acc1);
        acc1 = fmaf(fmaxf(a1.w + b1.w, 0.f), w.w, acc1);
    }
#pragma unroll
    for (int o = 8; o; o >>= 1) {
        acc0 += __shfl_xor_sync(0xFFFFFFFFu, acc0, o);
        acc1 += __shfl_xor_sync(0xFFFFFFFFu, acc1, o);
    }

    if (sub == 0) {
        float bb = b2[0];
        float s0 = acc0 + bb;
        scores_out[e0] = s0;
        atomicMax(&g_nmax[r0], f2ord(s0));
        if (has1) {
            float s1 = acc1 + bb;
            scores_out[e1] = s1;
            atomicMax(&g_nmax[r1], f2ord(s1));
        }
    }
}

// -------- kernel 4: deterministic fixed-point segment sum --------
__global__ void k_sum(const float* __restrict__ scores, const int* __restrict__ row, int E) {
    int e = blockIdx.x * blockDim.x + threadIdx.x;
    if (e >= E) return;
    int r = row[e];
    float m = ord2f(g_nmax[r]);
    float ex = expf(scores[e] - m);
    unsigned long long q = (unsigned long long)((double)ex * FIXSCALE);
    atomicAdd(&g_nsum[r], q);
}

// -------- kernel 5: outputs --------
__global__ void k_final(const float* __restrict__ scores, const int* __restrict__ row,
                        const float* __restrict__ u, const int* __restrict__ edge_mask,
                        const int* __restrict__ hier, float* __restrict__ out, int E) {
    int e = blockIdx.x * blockDim.x + threadIdx.x;
    if (e >= E) return;
    int r = row[e];
    float s = scores[e];
    float m = ord2f(g_nmax[r]);
    float ex = expf(s - m);
    float ssum = (float)((double)g_nsum[r] * (1.0 / FIXSCALE));
    float p = fminf(ex / ssum, 1.0f);

    float logits = logf(p) - log1pf(-p);
    float uu = u[e];
    float x = logits + (logf(uu) - log1pf(-uu));
    float y = 1.0f / (1.0f + expf(-x));
    bool hard = (y > 0.5f);

    int nm = hard ? (hier[0] + 1) : edge_mask[e];
    out[(size_t)E + e]     = hard ? 1.0f : 0.0f;
    out[(size_t)2 * E + e] = (float)nm;
    out[(size_t)3 * E + e] = (nm > 0) ? s : 0.0f;
    out[(size_t)4 * E + e] = (nm == -1) ? -s : 0.0f;
}

extern "C" void kernel_launch(void* const* d_in, const int* in_sizes, int n_in,
                              void* d_out, int out_size) {
    const float* h     = (const float*)d_in[0];
    const float* W1    = (const float*)d_in[1];
    const float* b1    = (const float*)d_in[2];
    const float* W2    = (const float*)d_in[3];
    const float* b2    = (const float*)d_in[4];
    const float* u     = (const float*)d_in[5];
    const int*   row   = (const int*)d_in[6];
    const int*   col   = (const int*)d_in[7];
    const int*   emask = (const int*)d_in[8];
    const int*   hier  = (const int*)d_in[9];
    float* out = (float*)d_out;
    int E = in_sizes[5];

    static bool attr_done = false;
    if (!attr_done) {
        cudaFuncSetAttribute(k_wgemm, cudaFuncAttributeMaxDynamicSharedMemorySize, SMEM_DYN);
        attr_done = true;
    }

    k_init<<<(NN + 255) / 256, 256>>>();
    k_split_a<<<(MPAD * 16 + 255) / 256, 256>>>(h);
    k_split_b<<<(128 * 256 + 255) / 256, 256>>>(W1);
    k_wgemm<<<dim3(8, MTILES), 256, SMEM_DYN>>>(b1);
    k_edge<<<(E * 8 + 255) / 256, 256>>>(row, col, W2, b2, out, E);
    k_sum<<<(E + 255) / 256, 256>>>(out, row, E);
    k_final<<<(E + 255) / 256, 256>>>(out, row, u, emask, hier, out, E);
}